// round 3
// baseline (speedup 1.0000x reference)
#include <cuda_runtime.h>
#include <math.h>

// Problem constants (fixed shapes)
#define NTIME   2000
#define NBATCH  128
#define INSIZE  256
#define NOUT    40
#define MROWS   (NTIME * NBATCH)   // 256000

#define TM      64                 // rows per block in GEMM
#define CCH     80                 // CRF chunks
#define LCH     25                 // timesteps per chunk (80*25 = 2000)

// Scratch (allocation-free rule: __device__ globals)
__device__ float g_M[CCH * 128 * 64];   // chunk matrices, layout [c][b][i'][i0]
__device__ float g_logZ[128];           // logZ[b] / NTIME

// Packed fp32x2 FMA (sm_100+): d.lo += a.lo*b.lo ; d.hi += a.hi*b.hi
__device__ __forceinline__ void fma2(unsigned long long& d,
                                     unsigned long long a,
                                     unsigned long long b) {
    asm("fma.rn.f32x2 %0, %1, %2, %0;" : "+l"(d) : "l"(a), "l"(b));
}

// ---------------- Kernel A: GEMM (M x 256 @ 256 x 40) + activations ----------------
// 128 threads/CTA, 2 CTAs/SM. Thread computes 4 rows x 5 cols with f32x2 FMAs.
// tid = rowg*8 + colg; thread rows = rowg + 16*m (m=0..3) so a warp's 4 x-addrs
// are CONSECUTIVE rows (odd stride 65 f4 -> distinct bank cols, conflict-free).
// W padded to 260 f32/row (65 f4): warp's 8 W rows at row-stride 5 hit bank
// cols {5*colg mod 8} = all distinct -> conflict-free broadcast loads.
#define WPAD 65                     // W row stride in float4 units (260 floats)
#define SMEM_WOFF 0
#define SMEM_BOFF (40 * WPAD * 16)               // 41,600
#define SMEM_XOFF (SMEM_BOFF + 160)              // 41,760
#define SMEM_TOTAL (SMEM_XOFF + 64 * 65 * 16)    // 108,320 B (x2 CTAs = 216,640)

__global__ __launch_bounds__(128, 2) void gemm_act_kernel(
    const float* __restrict__ x, const float* __restrict__ W,
    const float* __restrict__ bias, float* __restrict__ out)
{
    extern __shared__ char smem[];
    float* Ws  = (float*)(smem + SMEM_WOFF);
    float* bsh = (float*)(smem + SMEM_BOFF);
    float* xs  = (float*)(smem + SMEM_XOFF);
    const int tid  = threadIdx.x;
    const int row0 = blockIdx.x * TM;

    // Stage W (40 x 256 -> 40 x 260 padded) and x tile (64 x 256 -> 64 x 260)
    {
        const float4* Wg4 = (const float4*)W;
        float4* Ws4 = (float4*)Ws;
        #pragma unroll
        for (int i = 0; i < 20; i++) {
            int e = tid + i * 128;               // 2560 f4
            Ws4[(e >> 6) * WPAD + (e & 63)] = Wg4[e];
        }
        if (tid < NOUT) bsh[tid] = bias[tid];
        const float4* xg4 = (const float4*)x + (size_t)row0 * 64;
        float4* xs4 = (float4*)xs;
        #pragma unroll
        for (int i = 0; i < 32; i++) {
            int e = tid + i * 128;               // 4096 f4
            xs4[(e >> 6) * 65 + (e & 63)] = xg4[e];
        }
    }
    __syncthreads();

    const int rowg = tid >> 3;      // 0..15
    const int colg = tid & 7;       // 0..7
    const int c0   = colg * 5;      // 5 output cols per thread

    unsigned long long acc[4][5];
    #pragma unroll
    for (int m = 0; m < 4; m++)
        #pragma unroll
        for (int j = 0; j < 5; j++) acc[m][j] = 0ull;   // {0.f,0.f}

    const ulonglong2* Xs2 = (const ulonglong2*)xs;  // row stride 65 x 16B
    const ulonglong2* Ws2 = (const ulonglong2*)Ws;  // row stride 65 x 16B

    // Per k4 (4 k's): 5 W LDS.128 (x4 bcast, conflict-free) + 4 x LDS.128
    // (x8 bcast, conflict-free) + 40 FFMA2 (=80 FMA).
    #pragma unroll 4
    for (int k4 = 0; k4 < 64; k4++) {
        ulonglong2 wv[5];
        #pragma unroll
        for (int j = 0; j < 5; j++) wv[j] = Ws2[(c0 + j) * WPAD + k4];
        #pragma unroll
        for (int m = 0; m < 4; m++) {
            ulonglong2 xv = Xs2[(rowg + 16 * m) * 65 + k4];
            #pragma unroll
            for (int j = 0; j < 5; j++) {
                fma2(acc[m][j], xv.x, wv[j].x);
                fma2(acc[m][j], xv.y, wv[j].y);
            }
        }
    }

    // Epilogue: activations into smem (stride 41 -> conflict-free), coalesced store
    __syncthreads();
    float* ys = (float*)(smem + SMEM_XOFF);   // reuse x tile region: 64 x 41 f32
    #pragma unroll
    for (int m = 0; m < 4; m++) {
        int r = rowg + 16 * m;
        #pragma unroll
        for (int j = 0; j < 5; j++) {
            int c = c0 + j;
            float lo = __uint_as_float((unsigned int)acc[m][j]);
            float hi = __uint_as_float((unsigned int)(acc[m][j] >> 32));
            float y  = lo + hi + bsh[c];
            float v;
            if (c < 8) {
                float sp = (y > 20.0f) ? y : log1pf(__expf(y));
                v = ((c < 4) ? 1.0f : 0.1f) + sp;
            } else {
                // tanh(y) = 1 - 2/(exp(2y)+1); overflow-safe
                float e2 = __expf(2.0f * y);
                v = 5.0f * (1.0f - __fdividef(2.0f, e2 + 1.0f));
            }
            ys[r * 41 + c] = v;
        }
    }
    __syncthreads();
    float* outp = out + (size_t)row0 * NOUT;
    #pragma unroll
    for (int i = 0; i < 20; i++) {
        int e = tid + i * 128;                  // 2560 floats = 64 rows x 40 cols
        outp[e] = ys[(e / 40) * 41 + (e % 40)];
    }
}

// ---------------- Kernel B: per-chunk log-semiring matrix via basis propagation ----
// Thread = (batch b, chunk c, start-state i0). Propagates e_{i0} through LCH steps.
// The 8 threads sharing (b,c) are warp-adjacent -> identical loads broadcast.
__global__ __launch_bounds__(256) void crf_chunk_kernel(const float* __restrict__ out)
{
    int tid = blockIdx.x * 256 + threadIdx.x;
    int i0  = tid & 7;
    int gid = tid >> 3;
    int b   = gid & 127;
    int c   = gid >> 7;

    float v[8];
    #pragma unroll
    for (int j = 0; j < 8; j++) v[j] = (j == i0) ? 0.0f : -1e30f;

    const float* base = out + ((size_t)(c * LCH) * NBATCH + b) * NOUT + 8;
    for (int s = 0; s < LCH; s++) {
        float w[32];
        const float4* wp = (const float4*)base;
        #pragma unroll
        for (int q = 0; q < 8; q++) {
            float4 f = __ldg(wp + q);
            w[4*q+0] = f.x; w[4*q+1] = f.y; w[4*q+2] = f.z; w[4*q+3] = f.w;
        }
        float nv[8];
        #pragma unroll
        for (int i = 0; i < 4; i++) {
            float s8[8];
            #pragma unroll
            for (int j = 0; j < 8; j++) s8[j] = v[j] + w[i * 8 + j];
            // move_i: LSE over j != i, j != i+4  (6 terms)
            float m = -3.0e38f;
            #pragma unroll
            for (int j = 0; j < 8; j++) if (j != i && j != i + 4) m = fmaxf(m, s8[j]);
            float sum = 0.0f;
            #pragma unroll
            for (int j = 0; j < 8; j++) if (j != i && j != i + 4) sum += __expf(s8[j] - m);
            nv[i] = m + __logf(sum);
            // stay_i: LSE over j in {i, i+4}
            float a = s8[i], bb = s8[i + 4];
            float m2 = fmaxf(a, bb);
            nv[i + 4] = m2 + __logf(__expf(a - m2) + __expf(bb - m2));
        }
        #pragma unroll
        for (int j = 0; j < 8; j++) v[j] = nv[j];
        base += (size_t)NBATCH * NOUT;
    }
    // Store transposed: g_M[c][b][i'][i0] so kernel C reads contiguous rows
    float* mp = g_M + ((size_t)(c * 128 + b) * 8) * 8 + i0;
    #pragma unroll
    for (int ip = 0; ip < 8; ip++) mp[ip * 8] = v[ip];
}

// ---------------- Kernel C: sequential combine of 80 chunk matrices per batch -----
// Thread = (b, i'); 8 lanes per batch; fwd replicated per lane via shfl broadcast.
__global__ void crf_combine_kernel()
{
    int tid   = blockIdx.x * 64 + threadIdx.x;
    int ip    = tid & 7;
    int b     = tid >> 3;
    int lane  = threadIdx.x & 31;
    int gbase = lane & 24;

    float fwd[8];
    #pragma unroll
    for (int j = 0; j < 8; j++) fwd[j] = 0.0f;

    const float4* p0 = (const float4*)(g_M + ((size_t)b * 8 + ip) * 8);
    float4 r0 = p0[0], r1 = p0[1];
    for (int c = 0; c < CCH; c++) {
        float4 n0 = r0, n1 = r1;                // prefetch next chunk's row
        if (c + 1 < CCH) {
            const float4* pn = p0 + (size_t)(c + 1) * 2048;   // 128*64 f32 per chunk
            n0 = pn[0]; n1 = pn[1];
        }
        float s8[8];
        s8[0] = fwd[0] + r0.x; s8[1] = fwd[1] + r0.y; s8[2] = fwd[2] + r0.z; s8[3] = fwd[3] + r0.w;
        s8[4] = fwd[4] + r1.x; s8[5] = fwd[5] + r1.y; s8[6] = fwd[6] + r1.z; s8[7] = fwd[7] + r1.w;
        float m = s8[0];
        #pragma unroll
        for (int j = 1; j < 8; j++) m = fmaxf(m, s8[j]);
        float sum = 0.0f;
        #pragma unroll
        for (int j = 0; j < 8; j++) sum += __expf(s8[j] - m);
        float nv = m + __logf(sum);
        #pragma unroll
        for (int j = 0; j < 8; j++) fwd[j] = __shfl_sync(0xffffffffu, nv, gbase | j);
        r0 = n0; r1 = n1;
    }
    if (ip == 0) {
        float m = fwd[0];
        #pragma unroll
        for (int j = 1; j < 8; j++) m = fmaxf(m, fwd[j]);
        float sum = 0.0f;
        #pragma unroll
        for (int j = 0; j < 8; j++) sum += __expf(fwd[j] - m);
        g_logZ[b] = (m + __logf(sum)) * (1.0f / (float)NTIME);
    }
}

// ---------------- Kernel D: out[..., 8:40] -= logZ[b] ----------------
__global__ __launch_bounds__(256) void fixup_kernel(float* __restrict__ out)
{
    int idx  = blockIdx.x * 256 + threadIdx.x;   // 1,024,000 threads, 8 floats each
    int row  = idx >> 2;
    int part = idx & 3;
    float z  = g_logZ[row & 127];
    float4* p = (float4*)(out + (size_t)row * NOUT + 8 + part * 8);
    float4 a = p[0];
    a.x -= z; a.y -= z; a.z -= z; a.w -= z;
    p[0] = a;
    float4 b4 = p[1];
    b4.x -= z; b4.y -= z; b4.z -= z; b4.w -= z;
    p[1] = b4;
}

extern "C" void kernel_launch(void* const* d_in, const int* in_sizes, int n_in,
                              void* d_out, int out_size)
{
    const float* x    = (const float*)d_in[0];
    const float* W    = (const float*)d_in[1];
    const float* bias = (const float*)d_in[2];
    float* out        = (float*)d_out;

    // Idempotent; not a stream op, safe under graph capture.
    cudaFuncSetAttribute(gemm_act_kernel,
                         cudaFuncAttributeMaxDynamicSharedMemorySize, SMEM_TOTAL);

    gemm_act_kernel<<<MROWS / TM, 128, SMEM_TOTAL>>>(x, W, bias, out);
    crf_chunk_kernel<<<(128 * CCH * 8) / 256, 256>>>(out);
    crf_combine_kernel<<<16, 64>>>();
    fixup_kernel<<<(MROWS * 4) / 256, 256>>>(out);
}

// round 10
// speedup vs baseline: 1.8152x; 1.8152x over previous
#include <cuda_runtime.h>
#include <cuda_bf16.h>
#include <math.h>
#include <cstdint>

// Problem constants (fixed shapes)
#define NTIME   2000
#define NBATCH  128
#define INSIZE  256
#define NOUT    40
#define MROWS   (NTIME * NBATCH)   // 256000

#define TM      128                // rows per CTA in GEMM
#define CCH     80                 // CRF chunks
#define LCH     25                 // timesteps per chunk (80*25 = 2000)

// Scratch (allocation-free rule: __device__ globals)
__device__ float g_M[CCH * 128 * 64];            // chunk matrices [c][b][i'][i0]
__device__ float g_logZ[128];                    // logZ[b] / NTIME
__device__ unsigned long long g_Wsplit[2][2560]; // [hi/lo][nb][kb][lane] packed b-frags

// split one float into bf16 hi + bf16 residual
__device__ __forceinline__ void split1(float f, unsigned short& h, unsigned short& l) {
    __nv_bfloat16 hb = __float2bfloat16(f);
    float r = f - __bfloat162float(hb);
    __nv_bfloat16 lb = __float2bfloat16(r);
    h = __bfloat16_as_ushort(hb);
    l = __bfloat16_as_ushort(lb);
}

// ---------------- Kernel A0: W -> fragment-ordered split-bf16 ----------------
// Entry t = nb*512 + kb*32 + lane holds B-frag (b0,b1) for (kb, nb, lane):
// n = nb*8 + lane/4, q = lane%4, k = kb*16 + {2q, 2q+1, 2q+8, 2q+9}.
__global__ void wsplit_kernel(const float* __restrict__ W)
{
    int t = blockIdx.x * 256 + threadIdx.x;      // 0..2559
    if (t >= 2560) return;
    int lane = t & 31, kb = (t >> 5) & 15, nb = t >> 9;
    int n  = nb * 8 + (lane >> 2);
    int q  = lane & 3;
    int k0 = kb * 16 + q * 2;
    const float* wr = W + n * 256;
    float w0 = wr[k0], w1 = wr[k0 + 1], w2 = wr[k0 + 8], w3 = wr[k0 + 9];
    unsigned short h0, h1, h2, h3, l0, l1, l2, l3;
    split1(w0, h0, l0); split1(w1, h1, l1);
    split1(w2, h2, l2); split1(w3, h3, l3);
    g_Wsplit[0][t] = (unsigned long long)h0 | ((unsigned long long)h1 << 16)
                   | ((unsigned long long)h2 << 32) | ((unsigned long long)h3 << 48);
    g_Wsplit[1][t] = (unsigned long long)l0 | ((unsigned long long)l1 << 16)
                   | ((unsigned long long)l2 << 32) | ((unsigned long long)l3 << 48);
}

// ---------------- Kernel A: mma.sync split-bf16 GEMM + activations ----------------
// y[128 x 40] = x_tile @ W^T via m16n8k16 bf16 HMMA, fp32 accum.
// Warp w handles rows [w*16, w*16+16); 5 n-blocks cover N=40 exactly.
// A-frags loaded directly from global (split in-flight); B-frags via LDS.64
// from smem copy of g_Wsplit.
#define SMEM_WS   0                       // 40960 B: [hi 2560 | lo 2560] uint64
#define SMEM_YS   40960                   // 128 x 42 f32 = 21504 B
#define SMEM_BIAS 62464                   // 160 B
#define SMEM_A_TOTAL 62624

__device__ __forceinline__ void mma16816(float* d, const uint32_t* a,
                                         uint32_t b0, uint32_t b1) {
    asm volatile(
        "mma.sync.aligned.m16n8k16.row.col.f32.bf16.bf16.f32 "
        "{%0,%1,%2,%3}, {%4,%5,%6,%7}, {%8,%9}, {%0,%1,%2,%3};"
        : "+f"(d[0]), "+f"(d[1]), "+f"(d[2]), "+f"(d[3])
        : "r"(a[0]), "r"(a[1]), "r"(a[2]), "r"(a[3]), "r"(b0), "r"(b1));
}

// load float2 from global, split to packed bf16x2 hi/lo
__device__ __forceinline__ void load_a_pair(const float* p, uint32_t& hi, uint32_t& lo) {
    float2 f = *(const float2*)p;
    unsigned short h0, h1, l0, l1;
    split1(f.x, h0, l0);
    split1(f.y, h1, l1);
    hi = (uint32_t)h0 | ((uint32_t)h1 << 16);
    lo = (uint32_t)l0 | ((uint32_t)l1 << 16);
}

__device__ __forceinline__ float act(float y, int c) {
    if (c < 8) {
        float sp = (y > 20.0f) ? y : log1pf(__expf(y));
        return ((c < 4) ? 1.0f : 0.1f) + sp;
    }
    float e2 = __expf(2.0f * y);
    return 5.0f * (1.0f - __fdividef(2.0f, e2 + 1.0f));
}

__global__ __launch_bounds__(256, 2) void gemm_mma_kernel(
    const float* __restrict__ x, const float* __restrict__ bias,
    float* __restrict__ out)
{
    extern __shared__ char smem[];
    const int tid  = threadIdx.x;
    const int w    = tid >> 5;           // warp 0..7
    const int lane = tid & 31;
    const int gid  = lane >> 2;          // groupID 0..7
    const int tig  = lane & 3;           // thread-in-group 0..3
    const int row0 = blockIdx.x * TM;

    // Stage W frags (40960 B = 2560 float4) + bias
    {
        const float4* src = (const float4*)g_Wsplit;
        float4* dst = (float4*)(smem + SMEM_WS);
        #pragma unroll
        for (int i = 0; i < 10; i++) dst[tid + i * 256] = src[tid + i * 256];
        if (tid < NOUT) ((float*)(smem + SMEM_BIAS))[tid] = bias[tid];
    }
    __syncthreads();

    const unsigned long long* sWh = (const unsigned long long*)(smem + SMEM_WS);
    const unsigned long long* sWl = sWh + 2560;

    float d[5][4];
    #pragma unroll
    for (int nb = 0; nb < 5; nb++)
        #pragma unroll
        for (int j = 0; j < 4; j++) d[nb][j] = 0.0f;

    const float* xr = x + ((size_t)row0 + w * 16 + gid) * 256 + tig * 2;

    #pragma unroll 4
    for (int kb = 0; kb < 16; kb++) {
        const float* xp = xr + kb * 16;
        uint32_t ah[4], al[4];
        load_a_pair(xp,            ah[0], al[0]);   // (row g,   k 2t..)
        load_a_pair(xp + 2048,     ah[1], al[1]);   // (row g+8, k 2t..)
        load_a_pair(xp + 8,        ah[2], al[2]);   // (row g,   k 2t+8..)
        load_a_pair(xp + 2048 + 8, ah[3], al[3]);   // (row g+8, k 2t+8..)
        #pragma unroll
        for (int nb = 0; nb < 5; nb++) {
            int bi = (nb * 16 + kb) * 32 + lane;
            unsigned long long bh = sWh[bi];
            unsigned long long bl = sWl[bi];
            uint32_t b0h = (uint32_t)bh, b1h = (uint32_t)(bh >> 32);
            uint32_t b0l = (uint32_t)bl, b1l = (uint32_t)(bl >> 32);
            mma16816(d[nb], ah, b0h, b1h);
            mma16816(d[nb], ah, b0l, b1l);
            mma16816(d[nb], al, b0h, b1h);
        }
    }

    // Epilogue: bias + activations -> smem (stride 42), then coalesced store
    __syncthreads();   // done with W region? (ys is separate; sync orders nothing harmful)
    float* ys = (float*)(smem + SMEM_YS);
    const float* bsh = (const float*)(smem + SMEM_BIAS);
    int lr = w * 16 + gid;
    #pragma unroll
    for (int nb = 0; nb < 5; nb++) {
        int col = nb * 8 + tig * 2;
        float b0v = bsh[col], b1v = bsh[col + 1];
        ys[lr * 42 + col]            = act(d[nb][0] + b0v, col);
        ys[lr * 42 + col + 1]        = act(d[nb][1] + b1v, col + 1);
        ys[(lr + 8) * 42 + col]      = act(d[nb][2] + b0v, col);
        ys[(lr + 8) * 42 + col + 1]  = act(d[nb][3] + b1v, col + 1);
    }
    __syncthreads();
    float* outp = out + (size_t)row0 * NOUT;
    #pragma unroll
    for (int i = 0; i < 20; i++) {
        int e = tid + i * 256;                  // 5120 floats = 128 rows x 40 cols
        outp[e] = ys[(e / 40) * 42 + (e % 40)];
    }
}

// ---------------- Kernel B: per-chunk log-semiring matrix via basis propagation ----
__global__ __launch_bounds__(256) void crf_chunk_kernel(const float* __restrict__ out)
{
    int tid = blockIdx.x * 256 + threadIdx.x;
    int i0  = tid & 7;
    int gid = tid >> 3;
    int b   = gid & 127;
    int c   = gid >> 7;

    float v[8];
    #pragma unroll
    for (int j = 0; j < 8; j++) v[j] = (j == i0) ? 0.0f : -1e30f;

    const float* base = out + ((size_t)(c * LCH) * NBATCH + b) * NOUT + 8;
    for (int s = 0; s < LCH; s++) {
        float w[32];
        const float4* wp = (const float4*)base;
        #pragma unroll
        for (int q = 0; q < 8; q++) {
            float4 f = __ldg(wp + q);
            w[4*q+0] = f.x; w[4*q+1] = f.y; w[4*q+2] = f.z; w[4*q+3] = f.w;
        }
        float nv[8];
        #pragma unroll
        for (int i = 0; i < 4; i++) {
            float s8[8];
            #pragma unroll
            for (int j = 0; j < 8; j++) s8[j] = v[j] + w[i * 8 + j];
            float m = -3.0e38f;
            #pragma unroll
            for (int j = 0; j < 8; j++) if (j != i && j != i + 4) m = fmaxf(m, s8[j]);
            float sum = 0.0f;
            #pragma unroll
            for (int j = 0; j < 8; j++) if (j != i && j != i + 4) sum += __expf(s8[j] - m);
            nv[i] = m + __logf(sum);
            float a = s8[i], bb = s8[i + 4];
            float m2 = fmaxf(a, bb);
            nv[i + 4] = m2 + __logf(__expf(a - m2) + __expf(bb - m2));
        }
        #pragma unroll
        for (int j = 0; j < 8; j++) v[j] = nv[j];
        base += (size_t)NBATCH * NOUT;
    }
    float* mp = g_M + ((size_t)(c * 128 + b) * 8) * 8 + i0;
    #pragma unroll
    for (int ip = 0; ip < 8; ip++) mp[ip * 8] = v[ip];
}

// ---------------- Kernel C: sequential combine of 80 chunk matrices per batch -----
__global__ void crf_combine_kernel()
{
    int tid   = blockIdx.x * 64 + threadIdx.x;
    int ip    = tid & 7;
    int b     = tid >> 3;
    int lane  = threadIdx.x & 31;
    int gbase = lane & 24;

    float fwd[8];
    #pragma unroll
    for (int j = 0; j < 8; j++) fwd[j] = 0.0f;

    const float4* p0 = (const float4*)(g_M + ((size_t)b * 8 + ip) * 8);
    float4 r0 = p0[0], r1 = p0[1];
    for (int c = 0; c < CCH; c++) {
        float4 n0 = r0, n1 = r1;
        if (c + 1 < CCH) {
            const float4* pn = p0 + (size_t)(c + 1) * 2048;
            n0 = pn[0]; n1 = pn[1];
        }
        float s8[8];
        s8[0] = fwd[0] + r0.x; s8[1] = fwd[1] + r0.y; s8[2] = fwd[2] + r0.z; s8[3] = fwd[3] + r0.w;
        s8[4] = fwd[4] + r1.x; s8[5] = fwd[5] + r1.y; s8[6] = fwd[6] + r1.z; s8[7] = fwd[7] + r1.w;
        float m = s8[0];
        #pragma unroll
        for (int j = 1; j < 8; j++) m = fmaxf(m, s8[j]);
        float sum = 0.0f;
        #pragma unroll
        for (int j = 0; j < 8; j++) sum += __expf(s8[j] - m);
        float nv = m + __logf(sum);
        #pragma unroll
        for (int j = 0; j < 8; j++) fwd[j] = __shfl_sync(0xffffffffu, nv, gbase | j);
        r0 = n0; r1 = n1;
    }
    if (ip == 0) {
        float m = fwd[0];
        #pragma unroll
        for (int j = 1; j < 8; j++) m = fmaxf(m, fwd[j]);
        float sum = 0.0f;
        #pragma unroll
        for (int j = 0; j < 8; j++) sum += __expf(fwd[j] - m);
        g_logZ[b] = (m + __logf(sum)) * (1.0f / (float)NTIME);
    }
}

// ---------------- Kernel D: out[..., 8:40] -= logZ[b] ----------------
__global__ __launch_bounds__(256) void fixup_kernel(float* __restrict__ out)
{
    int idx  = blockIdx.x * 256 + threadIdx.x;
    int row  = idx >> 2;
    int part = idx & 3;
    float z  = g_logZ[row & 127];
    float4* p = (float4*)(out + (size_t)row * NOUT + 8 + part * 8);
    float4 a = p[0];
    a.x -= z; a.y -= z; a.z -= z; a.w -= z;
    p[0] = a;
    float4 b4 = p[1];
    b4.x -= z; b4.y -= z; b4.z -= z; b4.w -= z;
    p[1] = b4;
}

extern "C" void kernel_launch(void* const* d_in, const int* in_sizes, int n_in,
                              void* d_out, int out_size)
{
    const float* x    = (const float*)d_in[0];
    const float* W    = (const float*)d_in[1];
    const float* bias = (const float*)d_in[2];
    float* out        = (float*)d_out;

    cudaFuncSetAttribute(gemm_mma_kernel,
                         cudaFuncAttributeMaxDynamicSharedMemorySize, SMEM_A_TOTAL);

    wsplit_kernel<<<10, 256>>>(W);
    gemm_mma_kernel<<<MROWS / TM, 256, SMEM_A_TOTAL>>>(x, bias, out);
    crf_chunk_kernel<<<(128 * CCH * 8) / 256, 256>>>(out);
    crf_combine_kernel<<<16, 64>>>();
    fixup_kernel<<<(MROWS * 4) / 256, 256>>>(out);
}